// round 11
// baseline (speedup 1.0000x reference)
#include <cuda_runtime.h>
#include <cstdint>

#define NSEG   10000
#define NROWS  500000
#define D      128
#define BM     72
#define BLK    576
#define NWARP  (BLK / 32)                 // 18
#define NBLK   ((NSEG + BM - 1) / BM)     // 139
#define TOTW   (NBLK * NWARP)             // 2502
#define CK     ((NROWS + TOTW - 1) / TOTW) // 200 rows per warp
#define XS_STRIDE 132
#define SMEM_T ((D * D + BM * XS_STRIDE) * 4)   // 103552 bytes

__device__ float    g_sums[NSEG * D];     // zeroed by memset node each launch
__device__ unsigned g_bar;                // zeroed by memset node each launch

// graph may be int32 or int64 depending on jax x64 config.
// int32 layout: word[2*NSEG-1] = ends[NSEG-1] = N-1 (nonzero).
// int64 layout: word[2*NSEG-1] = high half of element NSEG-1 -> 0.
__device__ __forceinline__ bool graph_is64(const int* __restrict__ g) {
    return g[2 * NSEG - 1] == 0;
}
__device__ __forceinline__ int seg_start(const int* __restrict__ g, bool is64, int s) {
    return is64 ? g[4 * s] : g[2 * s];
}
__device__ __forceinline__ int seg_end(const int* __restrict__ g, bool is64, int s) {
    return is64 ? g[4 * s + 2] : g[2 * s + 1];
}

__device__ __forceinline__ float4 ldcs4(const float4* p) {
    float4 v;
    asm volatile("ld.global.cs.v4.f32 {%0,%1,%2,%3}, [%4];"
                 : "=f"(v.x), "=f"(v.y), "=f"(v.z), "=f"(v.w) : "l"(p));
    return v;
}

// ---------------------------------------------------------------------------
// FUSED kernel, 139 co-resident blocks (100KB smem -> 1/SM):
//  Phase 1: EQUAL-row streaming. Global warp gw owns rows [gw*200, +200):
//    unroll-8 LDG.128 (.cs), per-segment register partials flushed to g_sums
//    (STG.128 if segment wholly inside the chunk, atomicAdd at boundaries).
//  ws staging (transposed W -> smem) after own streaming, before barrier.
//  Grid barrier: threadfence + atomicAdd(g_bar), spin to NBLK (all blocks
//    resident -> deadlock-free; g_bar memset to 0 every launch).
//  Phase 2: stage xs tile from g_sums, register gemm with PACKED f32x2 FMA
//    (18 warps/SM now hides latency; halves FMA issue), + count*b epilogue.
// ---------------------------------------------------------------------------
__global__ void __launch_bounds__(BLK) fused_kernel(
    const float* __restrict__ input,
    const int*   __restrict__ graph,
    const float* __restrict__ W,
    const float* __restrict__ b,
    float*       __restrict__ out)
{
    extern __shared__ float sm[];
    float* ws = sm;            // ws[k*D + n]  (transposed W, 64KB)
    float* xs = sm + D * D;    // xs[m*XS_STRIDE + k]

    const int tid  = threadIdx.x;
    const int warp = tid >> 5;
    const int lane = tid & 31;
    const int m0   = blockIdx.x * BM;
    const int ns   = min(m0 + BM, NSEG) - m0;
    const bool is64 = graph_is64(graph);

    // --- Phase 1: balanced streaming sum -----------------------------------
    {
        const int gw  = blockIdx.x * NWARP + warp;
        const int a   = gw * CK;
        const int bnd = min(a + CK, NROWS);
        if (a < NROWS) {
            // Binary search (global, L2): largest seg with start <= a.
            int lo = 0, hi = NSEG - 1;
            while (lo < hi) {
                int mid = (lo + hi + 1) >> 1;
                if (seg_start(graph, is64, mid) <= a) lo = mid; else hi = mid - 1;
            }
            int seg = lo;
            int r   = a;
            while (r < bnd) {
                const int sE  = seg_end(graph, is64, seg);
                const int e   = min(sE + 1, bnd);
                const int len = e - r;

                const float4* p = (const float4*)input + (long long)r * 32 + lane;
                float4 acc = make_float4(0.f, 0.f, 0.f, 0.f);

                int i = 0;
                for (; i + 8 <= len; i += 8) {
                    float4 v0 = ldcs4(p + 0 * 32), v1 = ldcs4(p + 1 * 32);
                    float4 v2 = ldcs4(p + 2 * 32), v3 = ldcs4(p + 3 * 32);
                    float4 v4 = ldcs4(p + 4 * 32), v5 = ldcs4(p + 5 * 32);
                    float4 v6 = ldcs4(p + 6 * 32), v7 = ldcs4(p + 7 * 32);
                    acc.x += ((v0.x + v1.x) + (v2.x + v3.x)) + ((v4.x + v5.x) + (v6.x + v7.x));
                    acc.y += ((v0.y + v1.y) + (v2.y + v3.y)) + ((v4.y + v5.y) + (v6.y + v7.y));
                    acc.z += ((v0.z + v1.z) + (v2.z + v3.z)) + ((v4.z + v5.z) + (v6.z + v7.z));
                    acc.w += ((v0.w + v1.w) + (v2.w + v3.w)) + ((v4.w + v5.w) + (v6.w + v7.w));
                    p += 8 * 32;
                }
                for (; i < len; i++) {
                    float4 v = ldcs4(p);
                    acc.x += v.x; acc.y += v.y; acc.z += v.z; acc.w += v.w;
                    p += 32;
                }

                const int sS = seg_start(graph, is64, seg);
                float* dst = g_sums + (long long)seg * D + lane * 4;
                if (sS >= a && sE < bnd) {
                    *(float4*)dst = acc;                 // exclusive: plain store
                } else {
                    atomicAdd(dst + 0, acc.x);
                    atomicAdd(dst + 1, acc.y);
                    atomicAdd(dst + 2, acc.z);
                    atomicAdd(dst + 3, acc.w);
                }
                r = e;
                seg++;
            }
        }
    }

    // --- Stage transposed W into smem (hidden in streaming tail) -----------
    for (int lin = tid; lin < D * D / 4; lin += BLK) {
        int j = lin >> 7;          // 0..31
        int n = lin & 127;
        float4 w = ((const float4*)W)[n * 32 + j];
        ws[(4 * j + 0) * D + n] = w.x;
        ws[(4 * j + 1) * D + n] = w.y;
        ws[(4 * j + 2) * D + n] = w.z;
        ws[(4 * j + 3) * D + n] = w.w;
    }

    // --- Grid barrier -------------------------------------------------------
    __syncthreads();
    if (tid == 0) {
        __threadfence();                        // publish g_sums writes
        atomicAdd(&g_bar, 1u);
        volatile unsigned* vb = &g_bar;
        while (*vb < (unsigned)NBLK) __nanosleep(64);
        __threadfence();                        // acquire
    }
    __syncthreads();

    // --- Phase 2: stage xs, gemm with packed f32x2 --------------------------
    {
#pragma unroll
        for (int i = 0; i < (BM * D / 4) / BLK; i++) {   // 4 iters
            int lin = tid + i * BLK;
            int m   = lin >> 5;
            int k4  = lin & 31;
            int seg = m0 + m;
            float4 v = make_float4(0.f, 0.f, 0.f, 0.f);
            if (seg < NSEG) v = ((const float4*)g_sums)[seg * 32 + k4];
            *(float4*)(xs + m * XS_STRIDE + k4 * 4) = v;
        }
    }
    __syncthreads();

    const int tx = tid & 15;    // n-groups: [tx*4,+4) and [64+tx*4,+4)
    const int ty = tid >> 4;    // m-group: m = ty*2, ty*2+1 (ty 0..35)

    // acc2[m][j]: j=0,1 -> n-group0 pairs, j=2,3 -> n-group1 pairs.
    unsigned long long acc2[2][4];
#pragma unroll
    for (int i = 0; i < 2; i++)
#pragma unroll
        for (int j = 0; j < 4; j++) acc2[i][j] = 0ull;

    const float* xp0 = xs + (ty * 2 + 0) * XS_STRIDE;
    const float* xp1 = xs + (ty * 2 + 1) * XS_STRIDE;
    const float* wpf = ws + tx * 4;

#pragma unroll 2
    for (int k = 0; k < D; k += 4) {
        float4 xv0 = *(const float4*)(xp0 + k);
        float4 xv1 = *(const float4*)(xp1 + k);
        unsigned long long xx0[4], xx1[4];
        asm("mov.b64 %0, {%1, %1};" : "=l"(xx0[0]) : "f"(xv0.x));
        asm("mov.b64 %0, {%1, %1};" : "=l"(xx0[1]) : "f"(xv0.y));
        asm("mov.b64 %0, {%1, %1};" : "=l"(xx0[2]) : "f"(xv0.z));
        asm("mov.b64 %0, {%1, %1};" : "=l"(xx0[3]) : "f"(xv0.w));
        asm("mov.b64 %0, {%1, %1};" : "=l"(xx1[0]) : "f"(xv1.x));
        asm("mov.b64 %0, {%1, %1};" : "=l"(xx1[1]) : "f"(xv1.y));
        asm("mov.b64 %0, {%1, %1};" : "=l"(xx1[2]) : "f"(xv1.z));
        asm("mov.b64 %0, {%1, %1};" : "=l"(xx1[3]) : "f"(xv1.w));

#pragma unroll
        for (int kk = 0; kk < 4; kk++) {
            ulonglong2 w0 = *(const ulonglong2*)(wpf + (k + kk) * D);
            ulonglong2 w1 = *(const ulonglong2*)(wpf + (k + kk) * D + 64);
#define FMA2(dst, xx, w) \
            asm("fma.rn.f32x2 %0, %1, %2, %0;" : "+l"(dst) : "l"(xx), "l"(w))
            FMA2(acc2[0][0], xx0[kk], w0.x);
            FMA2(acc2[0][1], xx0[kk], w0.y);
            FMA2(acc2[0][2], xx0[kk], w1.x);
            FMA2(acc2[0][3], xx0[kk], w1.y);
            FMA2(acc2[1][0], xx1[kk], w0.x);
            FMA2(acc2[1][1], xx1[kk], w0.y);
            FMA2(acc2[1][2], xx1[kk], w1.x);
            FMA2(acc2[1][3], xx1[kk], w1.y);
#undef FMA2
        }
    }

    // Epilogue: + count * b.
    float4 b0 = ((const float4*)b)[tx];
    float4 b1 = ((const float4*)b)[16 + tx];

#pragma unroll
    for (int i = 0; i < 2; i++) {
        int m = ty * 2 + i;
        if (m >= ns) continue;
        int seg = m0 + m;
        float cnt = (float)(seg_end(graph, is64, seg) - seg_start(graph, is64, seg) + 1);

        float a0, a1, a2, a3, a4, a5, a6, a7;
        asm("mov.b64 {%0, %1}, %2;" : "=f"(a0), "=f"(a1) : "l"(acc2[i][0]));
        asm("mov.b64 {%0, %1}, %2;" : "=f"(a2), "=f"(a3) : "l"(acc2[i][1]));
        asm("mov.b64 {%0, %1}, %2;" : "=f"(a4), "=f"(a5) : "l"(acc2[i][2]));
        asm("mov.b64 {%0, %1}, %2;" : "=f"(a6), "=f"(a7) : "l"(acc2[i][3]));

        float4 o0, o1;
        o0.x = a0 + cnt * b0.x;
        o0.y = a1 + cnt * b0.y;
        o0.z = a2 + cnt * b0.z;
        o0.w = a3 + cnt * b0.w;
        o1.x = a4 + cnt * b1.x;
        o1.y = a5 + cnt * b1.y;
        o1.z = a6 + cnt * b1.z;
        o1.w = a7 + cnt * b1.w;

        float* op = out + (long long)seg * D;
        *(float4*)(op + tx * 4)      = o0;
        *(float4*)(op + 64 + tx * 4) = o1;
    }
}

extern "C" void kernel_launch(void* const* d_in, const int* in_sizes, int n_in,
                              void* d_out, int out_size) {
    const float* input = (const float*)d_in[0];
    const int*   graph = (const int*)  d_in[1];
    const float* W     = (const float*)d_in[2];
    const float* b     = (const float*)d_in[3];
    float*       out   = (float*)d_out;

    cudaFuncSetAttribute(fused_kernel,
                         cudaFuncAttributeMaxDynamicSharedMemorySize, SMEM_T);

    // Reset accumulator and barrier every launch (graph-capturable nodes).
    void* sums_ptr = nullptr;
    void* bar_ptr  = nullptr;
    cudaGetSymbolAddress(&sums_ptr, g_sums);
    cudaGetSymbolAddress(&bar_ptr,  g_bar);
    cudaMemsetAsync(sums_ptr, 0, (size_t)NSEG * D * sizeof(float));
    cudaMemsetAsync(bar_ptr,  0, sizeof(unsigned));

    fused_kernel<<<NBLK, BLK, SMEM_T>>>(input, graph, W, b, out);
}

// round 12
// speedup vs baseline: 1.0993x; 1.0993x over previous
#include <cuda_runtime.h>
#include <cstdint>

#define NSEG   10000
#define D      128
#define TBLK   16

__device__ float    g_WT[D * D];   // g_WT[k*D + n] = W[n*D + k]
__device__ unsigned g_wt_done;     // memset to 0 each launch

// graph may be int32 or int64 depending on jax x64 config.
// int32 layout: word[2*NSEG-1] = ends[NSEG-1] = N-1 (nonzero).
// int64 layout: word[2*NSEG-1] = high half of element NSEG-1 -> 0.
__device__ __forceinline__ void load_seg(const int* __restrict__ g, int s,
                                         int& st, int& en) {
    bool is64 = (g[2 * NSEG - 1] == 0);
    if (is64) {
        st = g[4 * s];
        en = g[4 * s + 2];
    } else {
        st = g[2 * s];
        en = g[2 * s + 1];
    }
}

// ---------------------------------------------------------------------------
// ONE kernel, block-per-segment, gemm fused per segment.
// Blocks [0,TBLK): transpose W -> g_WT, then release via atomic counter.
// Blocks [TBLK,...): segment s = blockIdx.x - TBLK, 128 threads:
//  A) stream rows [start,end] (R7 pattern: warp rl takes rows = rl mod 4,
//     16-stride unroll, 4 LDG.128 in flight, __ldcs evict-first so W stays
//     L1-resident), reduce across warps into xs[128] smem.
//  B) wait WT ready (first launch-wave contains the transpose blocks ->
//     no deadlock), then warp rl computes partial dot for its 32 k's:
//     lanes read WT4[k*32+lane] (coalesced LDG.128, L1 hit), xs[k] smem
//     broadcast, 4 independent float4 accumulators -> pk[rl][lane].
//  C) thread o sums 4 partials + cnt*b[o], coalesced store to out.
// The gemm work (L1 + FMA) hides inside the DRAM-stall issue slots of
// concurrently-streaming blocks (~12 blocks/SM resident).
// ---------------------------------------------------------------------------
__global__ void __launch_bounds__(128) fused_kernel(
    const float* __restrict__ input,
    const int*   __restrict__ graph,
    const float* __restrict__ W,
    const float* __restrict__ b,
    float*       __restrict__ out)
{
    const int tid = threadIdx.x;

    if (blockIdx.x < TBLK) {
        // Transpose W chunk, then publish.
        int base = blockIdx.x * (D * D / TBLK);          // 1024 elems/block
#pragma unroll
        for (int i = 0; i < (D * D / TBLK) / 128; i++) { // 8 iters
            int lin = base + tid + i * 128;
            int k = lin >> 7;
            int n = lin & 127;
            g_WT[lin] = W[n * D + k];
        }
        __syncthreads();
        __threadfence();
        if (tid == 0) atomicAdd(&g_wt_done, 1u);
        return;
    }

    const int s    = blockIdx.x - TBLK;
    const int lane = tid & 31;
    const int rl   = tid >> 5;   // warp 0..3

    int start, end;
    load_seg(graph, s, start, end);
    const int n   = end - start + 1;
    const float cnt = (float)n;

    __shared__ float4 red[4][32];
    __shared__ float  xs[D];
    __shared__ float  pk[4 * D];   // per-warp gemm partials

    // --- Phase A: stream the segment (R7 pattern, evict-first loads) -------
    {
        const float4* base = (const float4*)input + (long long)start * 32 + lane;
        float4 acc = make_float4(0.f, 0.f, 0.f, 0.f);
        int r = rl;
        for (; r + 12 < n; r += 16) {
            const float4* p = base + (long long)r * 32;
            float4 v0 = __ldcs(p + 0 * 32);
            float4 v1 = __ldcs(p + 4 * 32);
            float4 v2 = __ldcs(p + 8 * 32);
            float4 v3 = __ldcs(p + 12 * 32);
            acc.x += (v0.x + v1.x) + (v2.x + v3.x);
            acc.y += (v0.y + v1.y) + (v2.y + v3.y);
            acc.z += (v0.z + v1.z) + (v2.z + v3.z);
            acc.w += (v0.w + v1.w) + (v2.w + v3.w);
        }
        for (; r < n; r += 4) {
            float4 v = __ldcs(base + (long long)r * 32);
            acc.x += v.x; acc.y += v.y; acc.z += v.z; acc.w += v.w;
        }
        red[rl][lane] = acc;
    }
    __syncthreads();
    if (rl == 0) {
        float4 a = red[0][lane], b2 = red[1][lane];
        float4 c = red[2][lane], d  = red[3][lane];
        float4 t;
        t.x = (a.x + b2.x) + (c.x + d.x);
        t.y = (a.y + b2.y) + (c.y + d.y);
        t.z = (a.z + b2.z) + (c.z + d.z);
        t.w = (a.w + b2.w) + (c.w + d.w);
        ((float4*)xs)[lane] = t;
    }
    // Wait for g_WT (transpose blocks are in the first launch wave).
    if (tid == 0) {
        volatile unsigned* f = &g_wt_done;
        while (*f < (unsigned)TBLK) __nanosleep(32);
    }
    __syncthreads();
    __threadfence_block();   // order: xs visible; WT acquire via L1-miss path

    // --- Phase B: warp rl computes partial dot over k in [32*rl, 32*rl+32) --
    {
        const int k0 = rl * 32;
        const float4* wt4 = (const float4*)g_WT;
        float4 a0 = make_float4(0.f, 0.f, 0.f, 0.f);
        float4 a1 = make_float4(0.f, 0.f, 0.f, 0.f);
        float4 a2 = make_float4(0.f, 0.f, 0.f, 0.f);
        float4 a3 = make_float4(0.f, 0.f, 0.f, 0.f);
#pragma unroll
        for (int i = 0; i < 32; i += 4) {
            float4 w0 = __ldg(&wt4[(k0 + i + 0) * 32 + lane]);
            float4 w1 = __ldg(&wt4[(k0 + i + 1) * 32 + lane]);
            float4 w2 = __ldg(&wt4[(k0 + i + 2) * 32 + lane]);
            float4 w3 = __ldg(&wt4[(k0 + i + 3) * 32 + lane]);
            float x0 = xs[k0 + i + 0];
            float x1 = xs[k0 + i + 1];
            float x2 = xs[k0 + i + 2];
            float x3 = xs[k0 + i + 3];
            a0.x += x0 * w0.x; a0.y += x0 * w0.y; a0.z += x0 * w0.z; a0.w += x0 * w0.w;
            a1.x += x1 * w1.x; a1.y += x1 * w1.y; a1.z += x1 * w1.z; a1.w += x1 * w1.w;
            a2.x += x2 * w2.x; a2.y += x2 * w2.y; a2.z += x2 * w2.z; a2.w += x2 * w2.w;
            a3.x += x3 * w3.x; a3.y += x3 * w3.y; a3.z += x3 * w3.z; a3.w += x3 * w3.w;
        }
        float4 t;
        t.x = (a0.x + a1.x) + (a2.x + a3.x);
        t.y = (a0.y + a1.y) + (a2.y + a3.y);
        t.z = (a0.z + a1.z) + (a2.z + a3.z);
        t.w = (a0.w + a1.w) + (a2.w + a3.w);
        ((float4*)pk)[rl * 32 + lane] = t;    // pk[rl*128 + 4*lane + c]
    }
    __syncthreads();

    // --- Phase C: thread o combines 4 partials + bias ------------------------
    {
        const int o = tid;
        float r = (pk[0 * D + o] + pk[1 * D + o])
                + (pk[2 * D + o] + pk[3 * D + o]);
        r += cnt * __ldg(&b[o]);
        out[(long long)s * D + o] = r;
    }
}

extern "C" void kernel_launch(void* const* d_in, const int* in_sizes, int n_in,
                              void* d_out, int out_size) {
    const float* input = (const float*)d_in[0];
    const int*   graph = (const int*)  d_in[1];
    const float* W     = (const float*)d_in[2];
    const float* b     = (const float*)d_in[3];
    float*       out   = (float*)d_out;

    // Reset the WT-ready counter every launch (graph-capturable 4B memset).
    void* flag_ptr = nullptr;
    cudaGetSymbolAddress(&flag_ptr, g_wt_done);
    cudaMemsetAsync(flag_ptr, 0, sizeof(unsigned));

    fused_kernel<<<TBLK + NSEG, 128>>>(input, graph, W, b, out);
}

// round 14
// speedup vs baseline: 1.2533x; 1.1401x over previous
#include <cuda_runtime.h>
#include <cstdint>

#define NSEG   10000
#define D      128
#define BM     72
#define BLK_B  576
#define XS_STRIDE 132
#define NBLK_G ((NSEG + BM - 1) / BM)     // 139
#define SMEM_B ((D * D + BM * XS_STRIDE) * 4)   // 103552 bytes

__device__ float g_sums[NSEG * D];

// graph may be int32 or int64 depending on jax x64 config.
// int32 layout: word[2*NSEG-1] = ends[NSEG-1] = N-1 (nonzero).
// int64 layout: word[2*NSEG-1] = high half of element NSEG-1 -> 0.
__device__ __forceinline__ void load_seg(const int* __restrict__ g, int s,
                                         int& st, int& en) {
    bool is64 = (g[2 * NSEG - 1] == 0);
    if (is64) { st = g[4 * s];  en = g[4 * s + 2]; }
    else      { st = g[2 * s];  en = g[2 * s + 1]; }
}

// ---------------------------------------------------------------------------
// Kernel 1: block-per-segment sum (R7 body — protected; transpose prefix
// removed, the gemm now stages W itself inside the PDL overlap window).
// ---------------------------------------------------------------------------
__global__ void __launch_bounds__(128) sum_kernel(
    const float* __restrict__ input,
    const int*   __restrict__ graph)
{
    const int s    = blockIdx.x;
    const int c4   = threadIdx.x & 31;   // float4 column within row
    const int rl   = threadIdx.x >> 5;   // warp id 0..3

    int start, end;
    load_seg(graph, s, start, end);
    const int n = end - start + 1;

    const float4* base = (const float4*)input + (long long)start * 32 + c4;

    float4 acc = make_float4(0.f, 0.f, 0.f, 0.f);
    int r = rl;
    for (; r + 12 < n; r += 16) {
        const float4* p = base + (long long)r * 32;
        float4 v0 = p[0 * 32];
        float4 v1 = p[4 * 32];
        float4 v2 = p[8 * 32];
        float4 v3 = p[12 * 32];
        acc.x += (v0.x + v1.x) + (v2.x + v3.x);
        acc.y += (v0.y + v1.y) + (v2.y + v3.y);
        acc.z += (v0.z + v1.z) + (v2.z + v3.z);
        acc.w += (v0.w + v1.w) + (v2.w + v3.w);
    }
    for (; r < n; r += 4) {
        float4 v = base[(long long)r * 32];
        acc.x += v.x; acc.y += v.y; acc.z += v.z; acc.w += v.w;
    }

    __shared__ float4 red[4][32];
    red[rl][c4] = acc;
    __syncthreads();
    if (rl == 0) {
        float4 a = red[0][c4], b2 = red[1][c4], c = red[2][c4], d = red[3][c4];
        float4 t;
        t.x = (a.x + b2.x) + (c.x + d.x);
        t.y = (a.y + b2.y) + (c.y + d.y);
        t.z = (a.z + b2.z) + (c.z + d.z);
        t.w = (a.w + b2.w) + (c.w + d.w);
        ((float4*)g_sums)[s * 32 + c4] = t;
    }
}

// ---------------------------------------------------------------------------
// Kernel 2: out[m][n] = sum_k xs[m][k] * WT[k][n] + cnt_m * b[n]
// R7 mainloop (protected). NEW: launched with PDL. Prologue (W transpose
// into smem ws — independent of the sum) runs OVERLAPPED with the sum
// kernel's tail; cudaGridDependencySynchronize() gates only the g_sums read.
// ---------------------------------------------------------------------------
__global__ void __launch_bounds__(BLK_B) seg_gemm_kernel(
    const int*   __restrict__ graph,
    const float* __restrict__ W,
    const float* __restrict__ b,
    float*       __restrict__ out)
{
    extern __shared__ float sm[];
    float* ws = sm;            // ws[k*D + n]  (transposed W, 64KB)
    float* xs = sm + D * D;    // xs[m*XS_STRIDE + k]

    const int tid = threadIdx.x;
    const int m0  = blockIdx.x * BM;

    // --- Overlapped prologue: transpose W into ws ---------------------------
    // Thread reads W[n][4j..4j+3] (float4), writes 4 scalars ws[(4j+jj)*D+n].
    // n fast within warp -> conflict-free STS.
    for (int lin = tid; lin < D * D / 4; lin += BLK_B) {
        int j = lin >> 7;          // 0..31
        int n = lin & 127;
        float4 w = ((const float4*)W)[n * 32 + j];
        ws[(4 * j + 0) * D + n] = w.x;
        ws[(4 * j + 1) * D + n] = w.y;
        ws[(4 * j + 2) * D + n] = w.z;
        ws[(4 * j + 3) * D + n] = w.w;
    }

    // --- Wait for sum kernel's g_sums to be complete ------------------------
    cudaGridDependencySynchronize();

    // Stage x tile (72 rows x 32 float4 = 2304 = 4 * 576).
    {
#pragma unroll
        for (int i = 0; i < (BM * D / 4) / BLK_B; i++) {   // 4 iters
            int lin = tid + i * BLK_B;
            int m   = lin >> 5;
            int k4  = lin & 31;
            int seg = m0 + m;
            float4 v = make_float4(0.f, 0.f, 0.f, 0.f);
            if (seg < NSEG) v = ((const float4*)g_sums)[seg * 32 + k4];
            *(float4*)(xs + m * XS_STRIDE + k4 * 4) = v;
        }
    }
    __syncthreads();

    const int tx = tid & 15;    // n-groups: [tx*4, +4) and [64+tx*4, +4)
    const int ty = tid >> 4;    // m-group: m = ty*2, ty*2+1  (ty 0..35)

    float acc[2][8];
#pragma unroll
    for (int i = 0; i < 2; i++)
#pragma unroll
        for (int j = 0; j < 8; j++) acc[i][j] = 0.f;

    const float* xp0 = xs + (ty * 2 + 0) * XS_STRIDE;
    const float* xp1 = xs + (ty * 2 + 1) * XS_STRIDE;
    const float* wp  = ws + tx * 4;

#pragma unroll 2
    for (int k = 0; k < D; k += 4) {
        float4 xv0 = *(const float4*)(xp0 + k);
        float4 xv1 = *(const float4*)(xp1 + k);
        const float xr[2][4] = {
            {xv0.x, xv0.y, xv0.z, xv0.w},
            {xv1.x, xv1.y, xv1.z, xv1.w},
        };
#pragma unroll
        for (int kk = 0; kk < 4; kk++) {
            float4 w0 = *(const float4*)(wp + (k + kk) * D);
            float4 w1 = *(const float4*)(wp + (k + kk) * D + 64);
#pragma unroll
            for (int i = 0; i < 2; i++) {
                float x = xr[i][kk];
                acc[i][0] += x * w0.x; acc[i][1] += x * w0.y;
                acc[i][2] += x * w0.z; acc[i][3] += x * w0.w;
                acc[i][4] += x * w1.x; acc[i][5] += x * w1.y;
                acc[i][6] += x * w1.z; acc[i][7] += x * w1.w;
            }
        }
    }

    // Epilogue: + count * b. Two coalesced float4 groups at n=tx*4, 64+tx*4.
    float4 b0 = ((const float4*)b)[tx];
    float4 b1 = ((const float4*)b)[16 + tx];

#pragma unroll
    for (int i = 0; i < 2; i++) {
        int seg = m0 + ty * 2 + i;
        if (seg >= NSEG) continue;
        int st, en;
        load_seg(graph, seg, st, en);
        float cnt = (float)(en - st + 1);

        float4 o0, o1;
        o0.x = acc[i][0] + cnt * b0.x;
        o0.y = acc[i][1] + cnt * b0.y;
        o0.z = acc[i][2] + cnt * b0.z;
        o0.w = acc[i][3] + cnt * b0.w;
        o1.x = acc[i][4] + cnt * b1.x;
        o1.y = acc[i][5] + cnt * b1.y;
        o1.z = acc[i][6] + cnt * b1.z;
        o1.w = acc[i][7] + cnt * b1.w;

        float* op = out + (long long)seg * D;
        *(float4*)(op + tx * 4)      = o0;
        *(float4*)(op + 64 + tx * 4) = o1;
    }
}

extern "C" void kernel_launch(void* const* d_in, const int* in_sizes, int n_in,
                              void* d_out, int out_size) {
    const float* input = (const float*)d_in[0];
    const int*   graph = (const int*)  d_in[1];
    const float* W     = (const float*)d_in[2];
    const float* b     = (const float*)d_in[3];
    float*       out   = (float*)d_out;

    cudaFuncSetAttribute(seg_gemm_kernel,
                         cudaFuncAttributeMaxDynamicSharedMemorySize, SMEM_B);

    sum_kernel<<<NSEG, 128>>>(input, graph);

    // PDL launch: gemm prologue overlaps the sum kernel's tail.
    cudaLaunchConfig_t cfg = {};
    cfg.gridDim          = dim3(NBLK_G, 1, 1);
    cfg.blockDim         = dim3(BLK_B, 1, 1);
    cfg.dynamicSmemBytes = SMEM_B;
    cfg.stream           = 0;
    cudaLaunchAttribute attrs[1];
    attrs[0].id = cudaLaunchAttributeProgrammaticStreamSerialization;
    attrs[0].val.programmaticStreamSerializationAllowed = 1;
    cfg.attrs    = attrs;
    cfg.numAttrs = 1;
    cudaLaunchKernelEx(&cfg, seg_gemm_kernel, graph, W, b, out);
}